// round 6
// baseline (speedup 1.0000x reference)
#include <cuda_runtime.h>
#include <cstdint>

// Problem constants
#define BS 4096
#define D  100
#define DD (D*D)
#define H  16
#define H2 (H/2)
#define P  2

// Blocking
#define BPT 7            // b's per thread
#define BQ  4            // b-groups per block
#define BTILE (BPT*BQ)   // 28 b's per block
#define NBLK ((BS + BTILE - 1) / BTILE)  // 147 blocks ~ 148 SMs, single wave
#define NTHR (BQ*D)      // 400 threads

// j-chunking for smem weight staging
#define JT 10
#define NCHUNK (D/JT)                    // 10
#define CHUNK_U64 (JT*H2*D)              // 8000 u64
#define CHUNK_BYTES (CHUNK_U64*8)        // 64000
#define CHUNK_OPS (CHUNK_BYTES/16)       // 4000 x 16B
#define OPS_PER_THR (CHUNK_OPS/NTHR)     // 10

// smem layout (dynamic): [wbuf 2*64000][las 40000][xs 11200] = 179200 B
#define SM_WBUF 0
#define SM_LAS  (2*CHUNK_BYTES)
#define SM_XS   (SM_LAS + DD*4)
#define SM_TOTAL (SM_XS + BTILE*D*4)

typedef unsigned long long u64;

// Packed FMA: two independent IEEE fp32 FMAs per instruction (FFMA2). PTX-only on sm_103a.
#define FMA_F32X2(d, a, b, c) \
    asm("fma.rn.f32x2 %0, %1, %2, %3;" : "=l"(d) : "l"(a), "l"(b), "l"(c))
#define PACK_DUP_F32X2(out, v) \
    asm("mov.b64 %0, {%1, %1};" : "=l"(out) : "r"(__float_as_uint(v)))
#define UNPACK_F32X2(lo, hi, in) \
    asm("mov.b64 {%0, %1}, %2;" : "=r"(lo), "=r"(hi) : "l"(in))

#define CP_ASYNC16(dst_u32, src) \
    asm volatile("cp.async.cg.shared.global [%0], [%1], 16;" :: "r"(dst_u32), "l"(src))
#define CP_COMMIT() asm volatile("cp.async.commit_group;")
#define CP_WAIT1()  asm volatile("cp.async.wait_group 1;")
#define CP_WAIT0()  asm volatile("cp.async.wait_group 0;")

// Transposed weights (t-contiguous), device globals (no alloc). 16B-aligned for cp.async.
__device__ __align__(16) u64   g_W0p[D*H2*D];  // [j][i2][t] = pack(W0[t][2i2][j], W0[t][2i2+1][j])
__device__ float g_W1t[H*H*D];   // [i][j][t]
__device__ float g_W2t[P*H*D];   // [p][j][t]
__device__ float g_b0t[H*D];     // [i][t]
__device__ float g_b1t[H*D];     // [i][t]
__device__ float g_b2t[P*D];     // [p][t]

#define N_W0P (D*H2*D)
#define N_W1T (H*H*D)
#define N_W2T (P*H*D)
#define N_BT  (H*D)
#define N_B2T (P*D)
#define N_TOTAL (N_W0P + N_W1T + N_W2T + N_BT + N_BT + N_B2T)

__global__ void transpose_kernel(const float* __restrict__ W0, const float* __restrict__ b0,
                                 const float* __restrict__ W1, const float* __restrict__ b1,
                                 const float* __restrict__ W2, const float* __restrict__ b2) {
    int o = blockIdx.x * blockDim.x + threadIdx.x;
    if (o < N_W0P) {
        int j = o / (H2*D); int i2 = (o / D) % H2; int t = o % D;
        uint2 w;
        w.x = __float_as_uint(W0[(t*H + 2*i2    )*D + j]);
        w.y = __float_as_uint(W0[(t*H + 2*i2 + 1)*D + j]);
        g_W0p[o] = ((u64)w.y << 32) | (u64)w.x;
        return;
    }
    int o1 = o - N_W0P;
    if (o1 >= 0 && o1 < N_W1T) {
        int i = o1 / (H*D); int j = (o1 / D) % H; int t = o1 % D;
        g_W1t[o1] = W1[(t*H + i)*H + j];
        return;
    }
    int o2 = o1 - N_W1T;
    if (o2 >= 0 && o2 < N_W2T) {
        int p = o2 / (H*D); int j = (o2 / D) % H; int t = o2 % D;
        g_W2t[o2] = W2[(t*P + p)*H + j];
        return;
    }
    int o3 = o2 - N_W2T;
    if (o3 >= 0 && o3 < N_BT) { int i = o3 / D, t = o3 % D; g_b0t[o3] = b0[t*H + i]; return; }
    int o4 = o3 - N_BT;
    if (o4 >= 0 && o4 < N_BT) { int i = o4 / D, t = o4 % D; g_b1t[o4] = b1[t*H + i]; return; }
    int o5 = o4 - N_B2T - N_BT + N_B2T;  // = o4 - N_BT
    o5 = o4 - N_BT;
    if (o5 >= 0 && o5 < N_B2T) { int p = o5 / D, t = o5 % D; g_b2t[o5] = b2[t*P + p]; }
}

__global__ void __launch_bounds__(NTHR, 1)
fused_kernel(const float* __restrict__ x, const float* __restrict__ log_alpha,
             const float* __restrict__ noise, float* __restrict__ out) {
    extern __shared__ char smem_raw[];
    u64*   wsm = (u64*)(smem_raw + SM_WBUF);    // [2][JT][H2][D]
    float* las = (float*)(smem_raw + SM_LAS);   // [j][t] = -log_alpha[j][t]
    float* xs  = (float*)(smem_raw + SM_XS);    // [BTILE][D]

    const int tid = threadIdx.x;
    const int t   = tid % D;        // variable index; consecutive lanes -> consecutive t
    const int bq  = tid / D;
    const int blk = blockIdx.x;

    // Prefetch weight chunks 0,1 into smem via cp.async (overlaps with x/la staging)
    {
        const char* src0 = (const char*)g_W0p;
        uint32_t dst0 = (uint32_t)__cvta_generic_to_shared(smem_raw + SM_WBUF);
        #pragma unroll
        for (int p = 0; p < OPS_PER_THR; p++) {
            int off = (tid + p*NTHR) * 16;
            CP_ASYNC16(dst0 + off, src0 + off);
        }
        CP_COMMIT();
        #pragma unroll
        for (int p = 0; p < OPS_PER_THR; p++) {
            int off = (tid + p*NTHR) * 16;
            CP_ASYNC16(dst0 + CHUNK_BYTES + off, src0 + CHUNK_BYTES + off);
        }
        CP_COMMIT();
    }

    // Stage x tile and negated log_alpha
    for (int idx = tid; idx < BTILE*D; idx += NTHR) {
        int l = idx / D, j = idx % D;
        int src = min(blk*BTILE + (l / BPT)*BPT, BS - BPT) + (l % BPT);
        xs[idx] = x[src*D + j];
    }
    for (int idx = tid; idx < DD; idx += NTHR) las[idx] = -log_alpha[idx];
    __syncthreads();

    const int cb = min(blk*BTILE + bq*BPT, BS - BPT);
    const float* __restrict__ np   = noise + (size_t)cb * DD + t;   // + k*DD + j*D
    const float* __restrict__ xrow = xs + bq*BPT*D;                 // + k*D + j

    u64 acc2[BPT][H2];
    #pragma unroll
    for (int k = 0; k < BPT; k++)
        #pragma unroll
        for (int i2 = 0; i2 < H2; i2++) acc2[k][i2] = 0ull;

    // Depth-2 noise prefetch registers
    float nz0[BPT], nz1[BPT];
    #pragma unroll
    for (int k = 0; k < BPT; k++) nz0[k] = np[k*DD];
    #pragma unroll
    for (int k = 0; k < BPT; k++) nz1[k] = np[k*DD + D];

    // One layer-0 body: consume NZ for column j, prefetch column j+2 into NZ, FMA into acc2.
    #define L0_BODY(JCUR, JJ, NZ) do {                                          \
        const int j_ = (JCUR);                                                  \
        float negla = las[j_*D + t];                                            \
        const bool adj = (j_ != t);                                             \
        u64 vv[BPT];                                                            \
        _Pragma("unroll")                                                       \
        for (int k = 0; k < BPT; k++) {                                         \
            float xv = xrow[k*D + j_];                                          \
            float v  = (adj && (NZ[k] > negla)) ? xv : 0.f;                     \
            PACK_DUP_F32X2(vv[k], v);                                           \
        }                                                                       \
        const int jp_ = min(j_ + 2, D - 1);                                     \
        _Pragma("unroll")                                                       \
        for (int k = 0; k < BPT; k++) NZ[k] = np[k*DD + jp_*D];                 \
        _Pragma("unroll")                                                       \
        for (int i2 = 0; i2 < H2; i2++) {                                       \
            u64 w = wcs[((JJ)*H2 + i2)*D + t];                                  \
            _Pragma("unroll")                                                   \
            for (int k = 0; k < BPT; k++)                                       \
                FMA_F32X2(acc2[k][i2], w, vv[k], acc2[k][i2]);                  \
        }                                                                       \
    } while (0)

    // ---- Layer 0: chunked over j, weights double-buffered in smem ----
    #pragma unroll 1
    for (int c = 0; c < NCHUNK; c++) {
        if (c == NCHUNK - 1) { CP_WAIT0(); } else { CP_WAIT1(); }
        __syncthreads();                       // wbuf[c&1] visible to all
        const u64* __restrict__ wcs = wsm + (c & 1) * CHUNK_U64;
        const int jbase = c * JT;
        #pragma unroll
        for (int jj = 0; jj < JT; jj += 2) {
            L0_BODY(jbase + jj,     jj,     nz0);
            L0_BODY(jbase + jj + 1, jj + 1, nz1);
        }
        __syncthreads();                       // all warps done reading wbuf[c&1]
        if (c + 2 < NCHUNK) {
            const char* src = (const char*)g_W0p + (size_t)(c + 2) * CHUNK_BYTES;
            uint32_t dst = (uint32_t)__cvta_generic_to_shared(smem_raw + SM_WBUF + (c & 1) * CHUNK_BYTES);
            #pragma unroll
            for (int p = 0; p < OPS_PER_THR; p++) {
                int off = (tid + p*NTHR) * 16;
                CP_ASYNC16(dst + off, src + off);
            }
            CP_COMMIT();
        }
    }
    #undef L0_BODY

    // Unpack, bias + leaky_relu (slope 0.01), branch-free
    float acc[BPT][H];
    #pragma unroll
    for (int k = 0; k < BPT; k++)
        #pragma unroll
        for (int i2 = 0; i2 < H2; i2++) {
            unsigned lo, hi;
            UNPACK_F32X2(lo, hi, acc2[k][i2]);
            acc[k][2*i2]   = __uint_as_float(lo);
            acc[k][2*i2+1] = __uint_as_float(hi);
        }
    #pragma unroll
    for (int i = 0; i < H; i++) {
        float bv = g_b0t[i*D + t];
        #pragma unroll
        for (int k = 0; k < BPT; k++) {
            float h = acc[k][i] + bv;
            acc[k][i] = fmaf(0.01f, fminf(h, 0.f), fmaxf(h, 0.f));
        }
    }

    // ---- Layer 1 + output layer fused per i-slice ----
    float o0[BPT], o1[BPT];
    {
        float b20 = g_b2t[t], b21 = g_b2t[D + t];
        #pragma unroll
        for (int k = 0; k < BPT; k++) { o0[k] = b20; o1[k] = b21; }
    }
    #pragma unroll
    for (int i = 0; i < H; i++) {
        float t1[BPT];
        float bv = g_b1t[i*D + t];
        #pragma unroll
        for (int k = 0; k < BPT; k++) t1[k] = bv;
        #pragma unroll
        for (int j = 0; j < H; j++) {
            float w1 = g_W1t[(i*H + j)*D + t];
            #pragma unroll
            for (int k = 0; k < BPT; k++) t1[k] = fmaf(w1, acc[k][j], t1[k]);
        }
        float w20 = g_W2t[i*D + t];
        float w21 = g_W2t[(H + i)*D + t];
        #pragma unroll
        for (int k = 0; k < BPT; k++) {
            float h = fmaf(0.01f, fminf(t1[k], 0.f), fmaxf(t1[k], 0.f));
            o0[k] = fmaf(w20, h, o0[k]);
            o1[k] = fmaf(w21, h, o1[k]);
        }
    }

    // Store out[b][t][0..1] as one float2 (coalesced across t lanes)
    float2* __restrict__ o2p = (float2*)out;
    #pragma unroll
    for (int k = 0; k < BPT; k++) {
        o2p[(size_t)(cb + k)*D + t] = make_float2(o0[k], o1[k]);
    }
}

extern "C" void kernel_launch(void* const* d_in, const int* in_sizes, int n_in,
                              void* d_out, int out_size) {
    const float* x  = (const float*)d_in[0];
    const float* la = (const float*)d_in[1];
    const float* nz = (const float*)d_in[2];
    const float* W0 = (const float*)d_in[3];
    const float* b0 = (const float*)d_in[4];
    const float* W1 = (const float*)d_in[5];
    const float* b1 = (const float*)d_in[6];
    const float* W2 = (const float*)d_in[7];
    const float* b2 = (const float*)d_in[8];

    // Opt in to >48KB dynamic smem (module state change, capture-safe, idempotent)
    cudaFuncSetAttribute(fused_kernel, cudaFuncAttributeMaxDynamicSharedMemorySize, SM_TOTAL);

    transpose_kernel<<<(N_TOTAL + 255)/256, 256>>>(W0, b0, W1, b1, W2, b2);
    fused_kernel<<<NBLK, NTHR, SM_TOTAL>>>(x, la, nz, (float*)d_out);
}

// round 7
// speedup vs baseline: 1.2206x; 1.2206x over previous
#include <cuda_runtime.h>
#include <cstdint>

// Problem constants
#define BS 4096
#define D  100
#define DD (D*D)
#define H  16
#define H2 (H/2)
#define P  2

// Blocking (MLP pass)
#define BPT 7            // b's per thread
#define BQ  4            // b-groups per block
#define BTILE (BPT*BQ)   // 28 b's per block
#define NBLK ((BS + BTILE - 1) / BTILE)  // 147 blocks ~ 148 SMs, single wave
#define NTHR (BQ*D)      // 400 threads

// Dynamic smem for MLP pass: [mask uint4 BTILE*D][xs float BTILE*D]
#define SM_MSK 0
#define SM_XS  (BTILE*D*16)
#define SM_TOTAL (SM_XS + BTILE*D*4)   // 44800 + 11200 = 56000 B

typedef unsigned long long u64;

// Packed FMA: two independent IEEE fp32 FMAs per instruction (FFMA2). PTX-only on sm_103a.
#define FMA_F32X2(d, a, b, c) \
    asm("fma.rn.f32x2 %0, %1, %2, %3;" : "=l"(d) : "l"(a), "l"(b), "l"(c))
#define PACK_DUP_F32X2(out, v) \
    asm("mov.b64 %0, {%1, %1};" : "=l"(out) : "r"(__float_as_uint(v)))
#define UNPACK_F32X2(lo, hi, in) \
    asm("mov.b64 {%0, %1}, %2;" : "=r"(lo), "=r"(hi) : "l"(in))

// Transposed weights (t-contiguous), device globals (no alloc)
__device__ u64   g_W0p[D*H2*D];  // [j][i2][t] = pack(W0[t][2i2][j], W0[t][2i2+1][j])
__device__ float g_W1t[H*H*D];   // [i][j][t]
__device__ float g_W2t[P*H*D];   // [p][j][t]
__device__ float g_b0t[H*D];     // [i][t]
__device__ float g_b1t[H*D];     // [i][t]
__device__ float g_b2t[P*D];     // [p][t]

// Precomputed edge-mask bits: one uint4 (128 bits) per (b,j) row; bit t set iff
// (noise[b,j,t] + log_alpha[j,t] > 0) && (t != j).   6.55 MB scratch.
__device__ uint4 g_mask[BS*D];

#define N_W0P (D*H2*D)
#define N_W1T (H*H*D)
#define N_W2T (P*H*D)
#define N_BT  (H*D)
#define N_B2T (P*D)
#define N_TOTAL (N_W0P + N_W1T + N_W2T + N_BT + N_BT + N_B2T)

__global__ void transpose_kernel(const float* __restrict__ W0, const float* __restrict__ b0,
                                 const float* __restrict__ W1, const float* __restrict__ b1,
                                 const float* __restrict__ W2, const float* __restrict__ b2) {
    int o = blockIdx.x * blockDim.x + threadIdx.x;
    if (o < N_W0P) {
        int j = o / (H2*D); int i2 = (o / D) % H2; int t = o % D;
        uint2 w;
        w.x = __float_as_uint(W0[(t*H + 2*i2    )*D + j]);
        w.y = __float_as_uint(W0[(t*H + 2*i2 + 1)*D + j]);
        g_W0p[o] = ((u64)w.y << 32) | (u64)w.x;
        return;
    }
    int o1 = o - N_W0P;
    if (o1 >= 0 && o1 < N_W1T) {
        int i = o1 / (H*D); int j = (o1 / D) % H; int t = o1 % D;
        g_W1t[o1] = W1[(t*H + i)*H + j];
        return;
    }
    int o2 = o1 - N_W1T;
    if (o2 >= 0 && o2 < N_W2T) {
        int p = o2 / (H*D); int j = (o2 / D) % H; int t = o2 % D;
        g_W2t[o2] = W2[(t*P + p)*H + j];
        return;
    }
    int o3 = o2 - N_W2T;
    if (o3 >= 0 && o3 < N_BT) { int i = o3 / D, t = o3 % D; g_b0t[o3] = b0[t*H + i]; return; }
    int o4 = o3 - N_BT;
    if (o4 >= 0 && o4 < N_BT) { int i = o4 / D, t = o4 % D; g_b1t[o4] = b1[t*H + i]; return; }
    int o5 = o4 - N_BT;
    if (o5 >= 0 && o5 < N_B2T) { int p = o5 / D, t = o5 % D; g_b2t[o5] = b2[t*P + p]; }
}

// ---- Pass 1: stream noise once, emit edge-mask bits (HBM-roofline streaming) ----
#define MROWS (BS*D)
#define MB_THR 256
#define MB_GRID 2368
__global__ void __launch_bounds__(MB_THR)
mask_kernel(const float* __restrict__ noise, const float* __restrict__ log_alpha) {
    __shared__ float las[DD];   // raw log_alpha, 40KB
    for (int i = threadIdx.x; i < DD; i += MB_THR) las[i] = log_alpha[i];
    __syncthreads();

    const int lane  = threadIdx.x & 31;
    const int warp  = (blockIdx.x * MB_THR + threadIdx.x) >> 5;
    const int nwarp = (MB_GRID * MB_THR) >> 5;

    for (int row = warp; row < MROWS; row += nwarp) {
        const int j = row % D;                         // b = row / D
        const float* __restrict__ np = noise + (size_t)row * D;
        unsigned m[4];
        #pragma unroll
        for (int w = 0; w < 4; w++) {
            int t = w*32 + lane;
            bool p = false;
            if (t < D) p = (np[t] > -las[j*D + t]);    // sigmoid((la+nz)/tau)>0.5
            m[w] = __ballot_sync(0xffffffffu, p);
        }
        m[j >> 5] &= ~(1u << (j & 31));                // no self-loop (t == j)
        if (lane == 0) g_mask[row] = make_uint4(m[0], m[1], m[2], m[3]);
    }
}

// ---- Pass 2: fused MLP; masks from smem, weights from L1/L2, no DRAM-latency loads ----
__global__ void __launch_bounds__(NTHR, 1)
fused_kernel(const float* __restrict__ x, float* __restrict__ out) {
    extern __shared__ char smem_raw[];
    unsigned* msku = (unsigned*)(smem_raw + SM_MSK);   // [l][j][w] uint32, w = t>>5
    float*    xs   = (float*)(smem_raw + SM_XS);       // [l][j]

    const int tid = threadIdx.x;
    const int t   = tid % D;
    const int bq  = tid / D;
    const int blk = blockIdx.x;

    // Cooperative staging: mask tile (uint4, coalesced) + x tile.
    {
        uint4* msk4 = (uint4*)msku;
        for (int idx = tid; idx < BTILE*D; idx += NTHR) {
            int l = idx / D, j = idx % D;
            int src = min(blk*BTILE + (l / BPT)*BPT, BS - BPT) + (l % BPT);
            msk4[idx] = g_mask[src*D + j];
            xs[idx]   = x[src*D + j];
        }
    }
    __syncthreads();

    const int cb = min(blk*BTILE + bq*BPT, BS - BPT);
    const u64*   __restrict__ w0p  = g_W0p + t;           // + (j*H2 + i2)*D
    const float* __restrict__ xrow = xs + bq*BPT*D;       // + k*D + j
    const unsigned* __restrict__ mrow = msku + (bq*BPT*D)*4 + (t >> 5);  // + (k*D + j)*4
    const unsigned tb = t & 31;

    u64 acc2[BPT][H2];
    #pragma unroll
    for (int k = 0; k < BPT; k++)
        #pragma unroll
        for (int i2 = 0; i2 < H2; i2++) acc2[k][i2] = 0ull;

    // ---- Layer 0: masked per-variable matvec; mask bit-test from smem ----
    #pragma unroll 2
    for (int j = 0; j < D; j++) {
        u64 w2[H2];
        #pragma unroll
        for (int i2 = 0; i2 < H2; i2++) w2[i2] = w0p[(size_t)(j*H2 + i2)*D];
        u64 vv[BPT];
        #pragma unroll
        for (int k = 0; k < BPT; k++) {
            unsigned word = mrow[(k*D + j)*4];
            float v = ((word >> tb) & 1u) ? xrow[k*D + j] : 0.f;
            PACK_DUP_F32X2(vv[k], v);
        }
        #pragma unroll
        for (int i2 = 0; i2 < H2; i2++) {
            #pragma unroll
            for (int k = 0; k < BPT; k++)
                FMA_F32X2(acc2[k][i2], w2[i2], vv[k], acc2[k][i2]);
        }
    }

    // Unpack, bias + leaky_relu (slope 0.01), branch-free
    float acc[BPT][H];
    #pragma unroll
    for (int k = 0; k < BPT; k++)
        #pragma unroll
        for (int i2 = 0; i2 < H2; i2++) {
            unsigned lo, hi;
            UNPACK_F32X2(lo, hi, acc2[k][i2]);
            acc[k][2*i2]   = __uint_as_float(lo);
            acc[k][2*i2+1] = __uint_as_float(hi);
        }
    #pragma unroll
    for (int i = 0; i < H; i++) {
        float bv = g_b0t[i*D + t];
        #pragma unroll
        for (int k = 0; k < BPT; k++) {
            float h = acc[k][i] + bv;
            acc[k][i] = fmaf(0.01f, fminf(h, 0.f), fmaxf(h, 0.f));
        }
    }

    // ---- Layer 1 + output layer fused per i-slice ----
    float o0[BPT], o1[BPT];
    {
        float b20 = g_b2t[t], b21 = g_b2t[D + t];
        #pragma unroll
        for (int k = 0; k < BPT; k++) { o0[k] = b20; o1[k] = b21; }
    }
    #pragma unroll
    for (int i = 0; i < H; i++) {
        float t1[BPT];
        float bv = g_b1t[i*D + t];
        #pragma unroll
        for (int k = 0; k < BPT; k++) t1[k] = bv;
        #pragma unroll
        for (int j = 0; j < H; j++) {
            float w1 = g_W1t[(i*H + j)*D + t];
            #pragma unroll
            for (int k = 0; k < BPT; k++) t1[k] = fmaf(w1, acc[k][j], t1[k]);
        }
        float w20 = g_W2t[i*D + t];
        float w21 = g_W2t[(H + i)*D + t];
        #pragma unroll
        for (int k = 0; k < BPT; k++) {
            float h = fmaf(0.01f, fminf(t1[k], 0.f), fmaxf(t1[k], 0.f));
            o0[k] = fmaf(w20, h, o0[k]);
            o1[k] = fmaf(w21, h, o1[k]);
        }
    }

    // Store out[b][t][0..1] as one float2 (coalesced across t lanes)
    float2* __restrict__ o2p = (float2*)out;
    #pragma unroll
    for (int k = 0; k < BPT; k++) {
        o2p[(size_t)(cb + k)*D + t] = make_float2(o0[k], o1[k]);
    }
}

extern "C" void kernel_launch(void* const* d_in, const int* in_sizes, int n_in,
                              void* d_out, int out_size) {
    const float* x  = (const float*)d_in[0];
    const float* la = (const float*)d_in[1];
    const float* nz = (const float*)d_in[2];
    const float* W0 = (const float*)d_in[3];
    const float* b0 = (const float*)d_in[4];
    const float* W1 = (const float*)d_in[5];
    const float* b1 = (const float*)d_in[6];
    const float* W2 = (const float*)d_in[7];
    const float* b2 = (const float*)d_in[8];

    // Opt in to >48KB dynamic smem (idempotent, capture-safe)
    cudaFuncSetAttribute(fused_kernel, cudaFuncAttributeMaxDynamicSharedMemorySize, SM_TOTAL);

    transpose_kernel<<<(N_TOTAL + 255)/256, 256>>>(W0, b0, W1, b1, W2, b2);
    mask_kernel<<<MB_GRID, MB_THR>>>(nz, la);
    fused_kernel<<<NBLK, NTHR, SM_TOTAL>>>(x, (float*)d_out);
}

// round 12
// speedup vs baseline: 2.4994x; 2.0478x over previous
#include <cuda_runtime.h>
#include <cstdint>

// Problem constants
#define BS 4096
#define D  100
#define DD (D*D)
#define H  16
#define H2 (H/2)
#define P  2

// t-group decomposition: each block owns TL=25 variables -> W0 slice fits smem
#define TG 4             // number of t-groups
#define TL 25            // t's per group
// b blocking
#define BPT 4            // b's per thread
#define BQ  14           // b-groups per block
#define BTILE (BPT*BQ)   // 56 b's per tile
#define REPS 2           // b-tiles per block
#define NSG 37           // b-supertiles (37*2=74 tiles >= 4096/56)
#define NBLK (NSG*TG)    // 148 blocks = one wave
#define NTHR (TL*BQ)     // 350 threads

// smem layout
#define W0S_U64 (D*H2*TL)              // 20000 u64 = 160000 B
#define SM_W0  0
#define SM_MSK (W0S_U64*8)             // 160000
#define SM_XS  (SM_MSK + BTILE*D*4)    // +22400
#define SM_TOTAL (SM_XS + BTILE*D*4)   // 204800 B

typedef unsigned long long u64;

// Packed FMA: two independent IEEE fp32 FMAs per instruction (FFMA2). PTX-only on sm_103a.
#define FMA_F32X2(d, a, b, c) \
    asm("fma.rn.f32x2 %0, %1, %2, %3;" : "=l"(d) : "l"(a), "l"(b), "l"(c))
#define PACK_DUP_F32X2(out, v) \
    asm("mov.b64 %0, {%1, %1};" : "=l"(out) : "r"(__float_as_uint(v)))
#define UNPACK_F32X2(lo, hi, in) \
    asm("mov.b64 {%0, %1}, %2;" : "=r"(lo), "=r"(hi) : "l"(in))

// Transposed weights (t-contiguous), device globals (no alloc)
__device__ u64   g_W0p[D*H2*D];  // [j][i2][t] = pack(W0[t][2i2][j], W0[t][2i2+1][j])
__device__ float g_W1t[H*H*D];   // [i][j][t]
__device__ float g_W2t[P*H*D];   // [p][j][t]
__device__ float g_b0t[H*D];     // [i][t]
__device__ float g_b1t[H*D];     // [i][t]
__device__ float g_b2t[P*D];     // [p][t]

// Precomputed edge-mask bits: one uint4 (128 bits) per (b,j) row; bit t set iff
// (noise[b,j,t] + log_alpha[j,t] > 0) && (t != j).
__device__ uint4 g_mask[BS*D];

#define N_W0P (D*H2*D)
#define N_W1T (H*H*D)
#define N_W2T (P*H*D)
#define N_BT  (H*D)
#define N_B2T (P*D)
#define N_TOTAL (N_W0P + N_W1T + N_W2T + N_BT + N_BT + N_B2T)

__global__ void transpose_kernel(const float* __restrict__ W0, const float* __restrict__ b0,
                                 const float* __restrict__ W1, const float* __restrict__ b1,
                                 const float* __restrict__ W2, const float* __restrict__ b2) {
    int o = blockIdx.x * blockDim.x + threadIdx.x;
    if (o < N_W0P) {
        int j = o / (H2*D); int i2 = (o / D) % H2; int t = o % D;
        uint2 w;
        w.x = __float_as_uint(W0[(t*H + 2*i2    )*D + j]);
        w.y = __float_as_uint(W0[(t*H + 2*i2 + 1)*D + j]);
        g_W0p[o] = ((u64)w.y << 32) | (u64)w.x;
        return;
    }
    int o1 = o - N_W0P;
    if (o1 >= 0 && o1 < N_W1T) {
        int i = o1 / (H*D); int j = (o1 / D) % H; int t = o1 % D;
        g_W1t[o1] = W1[(t*H + i)*H + j];
        return;
    }
    int o2 = o1 - N_W1T;
    if (o2 >= 0 && o2 < N_W2T) {
        int p = o2 / (H*D); int j = (o2 / D) % H; int t = o2 % D;
        g_W2t[o2] = W2[(t*P + p)*H + j];
        return;
    }
    int o3 = o2 - N_W2T;
    if (o3 >= 0 && o3 < N_BT) { int i = o3 / D, t = o3 % D; g_b0t[o3] = b0[t*H + i]; return; }
    int o4 = o3 - N_BT;
    if (o4 >= 0 && o4 < N_BT) { int i = o4 / D, t = o4 % D; g_b1t[o4] = b1[t*H + i]; return; }
    int o5 = o4 - N_BT;
    if (o5 >= 0 && o5 < N_B2T) { int p = o5 / D, t = o5 % D; g_b2t[o5] = b2[t*P + p]; }
}

// ---- Pass 1: stream noise once, emit edge-mask bits ----
#define MROWS (BS*D)
#define MB_THR 256
#define MB_GRID 2368
__global__ void __launch_bounds__(MB_THR)
mask_kernel(const float* __restrict__ noise, const float* __restrict__ log_alpha) {
    __shared__ float las[DD];   // raw log_alpha, 40KB
    for (int i = threadIdx.x; i < DD; i += MB_THR) las[i] = log_alpha[i];
    __syncthreads();

    const int lane  = threadIdx.x & 31;
    const int warp  = (blockIdx.x * MB_THR + threadIdx.x) >> 5;
    const int nwarp = (MB_GRID * MB_THR) >> 5;

    for (int row = warp; row < MROWS; row += nwarp) {
        const int j = row % D;
        const float* __restrict__ np = noise + (size_t)row * D;
        unsigned m[4];
        #pragma unroll
        for (int w = 0; w < 4; w++) {
            int t = w*32 + lane;
            bool p = false;
            if (t < D) p = (np[t] > -las[j*D + t]);    // sigmoid((la+nz)/tau)>0.5
            m[w] = __ballot_sync(0xffffffffu, p);
        }
        m[j >> 5] &= ~(1u << (j & 31));                // no self-loop
        if (lane == 0) g_mask[row] = make_uint4(m[0], m[1], m[2], m[3]);
    }
}

// ---- Pass 2: fused MLP; W0 slice resident in smem, zero long-latency loads in loop ----
__global__ void __launch_bounds__(NTHR, 1)
fused_kernel(const float* __restrict__ x, float* __restrict__ out) {
    extern __shared__ char smem_raw[];
    u64*      wsm = (u64*)(smem_raw + SM_W0);       // [j][i2][tl]
    unsigned* msk = (unsigned*)(smem_raw + SM_MSK); // [l][j] 25-bit window
    float*    xs  = (float*)(smem_raw + SM_XS);     // [l][j]

    const int tid = threadIdx.x;
    const int tl  = tid % TL;            // t within group
    const int bq  = tid / TL;            // b-group
    const int tg  = blockIdx.x & 3;      // t-group
    const int sg  = blockIdx.x >> 2;     // b-supertile
    const int t   = tg*TL + tl;          // global variable index
    const int bitpos = tg*TL;
    const int w0i = bitpos >> 5, shw = bitpos & 31;

    // ---- One-time: stage this t-group's W0 slice (160KB) into smem ----
    for (int idx = tid; idx < W0S_U64; idx += NTHR) {
        int q = idx / TL, s = idx % TL;            // q = j*H2+i2
        wsm[idx] = g_W0p[(size_t)q*D + bitpos + s];
    }

    for (int rep = 0; rep < REPS; rep++) {
        const int bt  = sg*REPS + rep;                       // 0..73
        const int cb0 = min(bt*BTILE, BS - BTILE);           // tile base (tail clamp, dup writes identical)

        __syncthreads();   // previous rep's readers done (also orders W0 staging on rep 0)
        // Stage mask window + x tile
        for (int idx = tid; idx < BTILE*D; idx += NTHR) {
            int l = idx / D, j = idx % D;
            int b = cb0 + l;
            uint4 m = g_mask[(size_t)b*D + j];
            unsigned mw[4] = {m.x, m.y, m.z, m.w};
            unsigned lo = mw[w0i];
            unsigned hi = (w0i < 3) ? mw[w0i + 1] : 0u;
            msk[idx] = __funnelshift_r(lo, hi, shw);         // bits [tg*25, tg*25+25)
            xs[idx]  = x[(size_t)b*D + j];
        }
        __syncthreads();

        const int cb = cb0 + bq*BPT;
        const unsigned* __restrict__ mskp = msk + bq*BPT*D;  // + k*D + j
        const float*    __restrict__ xsp  = xs  + bq*BPT*D;
        const u64*      __restrict__ wp   = wsm + tl;        // + (j*H2+i2)*TL

        u64 acc2[BPT][H2];
        #pragma unroll
        for (int k = 0; k < BPT; k++)
            #pragma unroll
            for (int i2 = 0; i2 < H2; i2++) acc2[k][i2] = 0ull;

        // ---- Layer 0: everything from smem ----
        #pragma unroll 2
        for (int j = 0; j < D; j++) {
            u64 w2[H2];
            #pragma unroll
            for (int i2 = 0; i2 < H2; i2++) w2[i2] = wp[(j*H2 + i2)*TL];
            u64 vv[BPT];
            #pragma unroll
            for (int k = 0; k < BPT; k++) {
                unsigned win = mskp[k*D + j];
                float v = ((win >> tl) & 1u) ? xsp[k*D + j] : 0.f;
                PACK_DUP_F32X2(vv[k], v);
            }
            #pragma unroll
            for (int i2 = 0; i2 < H2; i2++)
                #pragma unroll
                for (int k = 0; k < BPT; k++)
                    FMA_F32X2(acc2[k][i2], w2[i2], vv[k], acc2[k][i2]);
        }

        // Unpack, bias + leaky_relu (slope 0.01)
        float acc[BPT][H];
        #pragma unroll
        for (int k = 0; k < BPT; k++)
            #pragma unroll
            for (int i2 = 0; i2 < H2; i2++) {
                unsigned lo, hi;
                UNPACK_F32X2(lo, hi, acc2[k][i2]);
                acc[k][2*i2]   = __uint_as_float(lo);
                acc[k][2*i2+1] = __uint_as_float(hi);
            }
        #pragma unroll
        for (int i = 0; i < H; i++) {
            float bv = g_b0t[i*D + t];
            #pragma unroll
            for (int k = 0; k < BPT; k++) {
                float h = acc[k][i] + bv;
                acc[k][i] = fmaf(0.01f, fminf(h, 0.f), fmaxf(h, 0.f));
            }
        }

        // ---- Layer 1 + output layer fused per i-slice ----
        float o0[BPT], o1[BPT];
        {
            float b20 = g_b2t[t], b21 = g_b2t[D + t];
            #pragma unroll
            for (int k = 0; k < BPT; k++) { o0[k] = b20; o1[k] = b21; }
        }
        #pragma unroll
        for (int i = 0; i < H; i++) {
            float t1[BPT];
            float bv = g_b1t[i*D + t];
            #pragma unroll
            for (int k = 0; k < BPT; k++) t1[k] = bv;
            #pragma unroll
            for (int j = 0; j < H; j++) {
                float w1 = g_W1t[(i*H + j)*D + t];
                #pragma unroll
                for (int k = 0; k < BPT; k++) t1[k] = fmaf(w1, acc[k][j], t1[k]);
            }
            float w20 = g_W2t[i*D + t];
            float w21 = g_W2t[(H + i)*D + t];
            #pragma unroll
            for (int k = 0; k < BPT; k++) {
                float h = fmaf(0.01f, fminf(t1[k], 0.f), fmaxf(t1[k], 0.f));
                o0[k] = fmaf(w20, h, o0[k]);
                o1[k] = fmaf(w21, h, o1[k]);
            }
        }

        // Store out[b][t][0..1] (float2, contiguous across tl lanes)
        float2* __restrict__ o2p = (float2*)out;
        #pragma unroll
        for (int k = 0; k < BPT; k++)
            o2p[(size_t)(cb + k)*D + t] = make_float2(o0[k], o1[k]);
    }
}

extern "C" void kernel_launch(void* const* d_in, const int* in_sizes, int n_in,
                              void* d_out, int out_size) {
    const float* x  = (const float*)d_in[0];
    const float* la = (const float*)d_in[1];
    const float* nz = (const float*)d_in[2];
    const float* W0 = (const float*)d_in[3];
    const float* b0 = (const float*)d_in[4];
    const float* W1 = (const float*)d_in[5];
    const float* b1 = (const float*)d_in[6];
    const float* W2 = (const float*)d_in[7];
    const float* b2 = (const float*)d_in[8];

    cudaFuncSetAttribute(fused_kernel, cudaFuncAttributeMaxDynamicSharedMemorySize, SM_TOTAL);

    transpose_kernel<<<(N_TOTAL + 255)/256, 256>>>(W0, b0, W1, b1, W2, b2);
    mask_kernel<<<MB_GRID, MB_THR>>>(nz, la);
    fused_kernel<<<NBLK, NTHR, SM_TOTAL>>>(x, (float*)d_out);
}